// round 3
// baseline (speedup 1.0000x reference)
#include <cuda_runtime.h>
#include <cstdint>

#define BB 512
#define RR 264
#define KK 32
#define SS 9
#define RPAD 268                 // k-row stride in floats; 268*4=1072 B (16B aligned)
#define NTHREADS 384
#define NACT 363                 // 33 tr-tiles * 11 tc-tiles
#define COLS_PER_CTA 132         // 2 CTAs per batch along columns

typedef unsigned long long ull;

__device__ __constant__ int   c_ends[SS]  = {28, 58, 92, 121, 150, 180, 210, 240, 264};
__device__ __constant__ float c_sizes[SS] = {28.f, 30.f, 34.f, 29.f, 29.f, 30.f, 30.f, 30.f, 24.f};

__device__ __forceinline__ ull fma2(ull a, ull b, ull c) {
    ull d;
    asm("fma.rn.f32x2 %0, %1, %2, %3;" : "=l"(d) : "l"(a), "l"(b), "l"(c));
    return d;
}
__device__ __forceinline__ ull dup2(float x) {
    ull d;
    asm("mov.b64 %0, {%1, %1};" : "=l"(d) : "f"(x));
    return d;
}
// mask halves of a packed f32x2 by two predicates
__device__ __forceinline__ ull mask2(ull v, bool p0, bool p1) {
    float lo = __uint_as_float((unsigned)(v & 0xffffffffull));
    float hi = __uint_as_float((unsigned)(v >> 32));
    lo = p0 ? lo : 0.0f;
    hi = p1 ? hi : 0.0f;
    return ((ull)__float_as_uint(hi) << 32) | (ull)__float_as_uint(lo);
}

extern "C" __global__ void __launch_bounds__(NTHREADS, 1)
gram_kernel(const float* __restrict__ E, float* __restrict__ out)
{
    float* intra = out;
    float* inter = out + (size_t)BB * RR * RR;
    float* adj   = inter + (size_t)BB * SS * SS;

    __shared__ float sT[KK * RPAD];        // E^T: sT[k*RPAD + r]
    __shared__ int   sSeg[RR];
    __shared__ float sSum[SS * KK];

    const int b   = blockIdx.y;
    const int cx  = blockIdx.x;            // column half: 0 or 1
    const int tid = threadIdx.x;
    const float* Eb = E + (size_t)b * (RR * KK);

    // ---- build transposed smem tile: read float4 along k, scatter-store ----
    for (int i = tid; i < (RR * KK) / 4; i += NTHREADS) {
        int row = i >> 3;                  // 8 float4 per row
        int k4  = (i & 7) * 4;
        float4 v = reinterpret_cast<const float4*>(Eb)[i];
        sT[(k4 + 0) * RPAD + row] = v.x;
        sT[(k4 + 1) * RPAD + row] = v.y;
        sT[(k4 + 2) * RPAD + row] = v.z;
        sT[(k4 + 3) * RPAD + row] = v.w;
    }
    for (int i = tid; i < RR; i += NTHREADS) {
        int s = 0;
        #pragma unroll
        for (int j = 0; j < SS; j++) s += (i >= c_ends[j]) ? 1 : 0;
        sSeg[i] = s;
    }
    __syncthreads();

    // ---- inter-network block means (only cx==0 CTAs) ----
    if (cx == 0) {
        for (int i = tid; i < SS * KK; i += NTHREADS) {
            int s  = i >> 5;
            int d  = i & 31;
            int st = (s == 0) ? 0 : c_ends[s - 1];
            int en = c_ends[s];
            float a = 0.0f;
            const float* kp = &sT[d * RPAD];
            for (int r = st; r < en; r++) a += kp[r];
            sSum[i] = a;
        }
        __syncthreads();
        if (tid < SS * SS) {
            int s = tid / SS, t = tid % SS;
            float a = 0.0f;
            #pragma unroll
            for (int d = 0; d < KK; d++)
                a += sSum[s * KK + d] * sSum[t * KK + d];
            inter[(size_t)b * SS * SS + tid] = a / (c_sizes[s] * c_sizes[t]);
        }
    }

    if (tid >= NACT) return;

    const int tc = tid % 11;               // column-tile id
    const int tr = tid / 11;               // row-tile id
    const int r0 = 8 * tr;                 // 8 rows
    const int cb = COLS_PER_CTA * cx + 4 * tc;  // base of quad 0 (quads at +44*q)

    // 48 packed accumulators: acc[i][jp] = (out[r0+i][cq+2m], out[r0+i][cq+2m+1])
    ull acc[8][6];
    #pragma unroll
    for (int i = 0; i < 8; i++)
        #pragma unroll
        for (int j = 0; j < 6; j++) acc[i][j] = 0ull;

    #pragma unroll 2
    for (int k = 0; k < KK; k++) {
        const float* kp = &sT[k * RPAD];
        // a-frag: 8 row values (2x LDS.128)
        float4 a0 = *reinterpret_cast<const float4*>(kp + r0);
        float4 a1 = *reinterpret_cast<const float4*>(kp + r0 + 4);
        // b-frag: 3 column quads = 6 column-pairs (3x LDS.128)
        ull bf[6];
        #pragma unroll
        for (int q = 0; q < 3; q++) {
            ulonglong2 t2 = *reinterpret_cast<const ulonglong2*>(kp + cb + 44 * q);
            bf[2 * q] = t2.x; bf[2 * q + 1] = t2.y;
        }
        float av[8] = {a0.x, a0.y, a0.z, a0.w, a1.x, a1.y, a1.z, a1.w};
        #pragma unroll
        for (int i = 0; i < 8; i++) {
            ull d = dup2(av[i]);
            #pragma unroll
            for (int j = 0; j < 6; j++)
                acc[i][j] = fma2(d, bf[j], acc[i][j]);
        }
    }

    // ---- epilogue: coalesced STG.128 per quad ----
    int segc[6][2];
    #pragma unroll
    for (int j = 0; j < 6; j++) {
        int c = cb + 44 * (j >> 1) + 2 * (j & 1);
        segc[j][0] = sSeg[c];
        segc[j][1] = sSeg[c + 1];
    }

    #pragma unroll
    for (int i = 0; i < 8; i++) {
        const int r = r0 + i;
        const int segr = sSeg[r];
        float* arow = adj   + (((size_t)b * RR + r) * RR);
        float* irow = intra + (((size_t)b * RR + r) * RR);
        #pragma unroll
        for (int q = 0; q < 3; q++) {
            int c = cb + 44 * q;
            ulonglong2 av;
            av.x = acc[i][2 * q];
            av.y = acc[i][2 * q + 1];
            *reinterpret_cast<ulonglong2*>(arow + c) = av;
            ulonglong2 iv;
            iv.x = mask2(av.x, segc[2 * q][0] == segr,     segc[2 * q][1] == segr);
            iv.y = mask2(av.y, segc[2 * q + 1][0] == segr, segc[2 * q + 1][1] == segr);
            *reinterpret_cast<ulonglong2*>(irow + c) = iv;
        }
    }
}

extern "C" void kernel_launch(void* const* d_in, const int* in_sizes, int n_in,
                              void* d_out, int out_size)
{
    (void)in_sizes; (void)n_in; (void)out_size;
    const float* E = (const float*)d_in[0];
    float* out = (float*)d_out;

    dim3 grid(2, BB);
    gram_kernel<<<grid, NTHREADS>>>(E, out);
}

// round 4
// speedup vs baseline: 1.2490x; 1.2490x over previous
#include <cuda_runtime.h>
#include <cstdint>

#define BB 512
#define RR 264
#define KK 32
#define SS 9
#define RSTRIDE 36            // padded row stride in floats (144 B, 16B-aligned)
#define NSPLIT 4
#define ROWS_PER (RR / NSPLIT) // 66
#define NTHREADS 288

typedef unsigned long long ull;

__device__ __constant__ int   c_ends[SS]  = {28, 58, 92, 121, 150, 180, 210, 240, 264};
__device__ __constant__ int   c_starts[SS]= {0, 28, 58, 92, 121, 150, 180, 210, 240};
__device__ __constant__ float c_sizes[SS] = {28.f, 30.f, 34.f, 29.f, 29.f, 30.f, 30.f, 30.f, 24.f};

__device__ __forceinline__ ull fma2(ull a, ull b, ull c) {
    ull d;
    asm("fma.rn.f32x2 %0, %1, %2, %3;" : "=l"(d) : "l"(a), "l"(b), "l"(c));
    return d;
}
__device__ __forceinline__ ull add2(ull a, ull b) {
    ull d;
    asm("add.rn.f32x2 %0, %1, %2;" : "=l"(d) : "l"(a), "l"(b));
    return d;
}
__device__ __forceinline__ float sum2(ull a) {
    return __uint_as_float((unsigned)(a & 0xffffffffull)) +
           __uint_as_float((unsigned)(a >> 32));
}

extern "C" __global__ void __launch_bounds__(NTHREADS, 3)
gram_kernel(const float* __restrict__ E, float* __restrict__ out)
{
    float* intra = out;
    float* inter = out + (size_t)BB * RR * RR;
    float* adj   = inter + (size_t)BB * SS * SS;

    extern __shared__ float sE[];          // [RR][RSTRIDE]
    __shared__ float sSum[SS * KK];

    const int b     = blockIdx.y;
    const int split = blockIdx.x;
    const int tid   = threadIdx.x;
    const float* Eb = E + (size_t)b * (RR * KK);

    // ---- cooperative load of E[b] into padded smem (float4 coalesced) ----
    for (int i = tid; i < (RR * KK) / 4; i += NTHREADS) {
        float4 v = reinterpret_cast<const float4*>(Eb)[i];
        int row = i >> 3, kq = i & 7;
        *reinterpret_cast<float4*>(&sE[row * RSTRIDE + kq * 4]) = v;
    }
    __syncthreads();

    const bool active = (tid < RR);
    const int  cc     = active ? tid : 0;

    // this thread's column vector: 8 x LDS.128 -> 16 packed f32x2
    ull bv[16];
    #pragma unroll
    for (int q = 0; q < 8; q++) {
        ulonglong2 t2 = *reinterpret_cast<const ulonglong2*>(&sE[cc * RSTRIDE + 4 * q]);
        bv[2 * q] = t2.x; bv[2 * q + 1] = t2.y;
    }

    // segment range of this column (register-resident intra mask)
    int seg = 0;
    #pragma unroll
    for (int j = 0; j < SS; j++) seg += (cc >= c_ends[j]) ? 1 : 0;
    const int lo = c_starts[seg];
    const int hi = c_ends[seg];

    const int r0 = split * ROWS_PER;
    float* adjp   = adj   + (((size_t)b * RR + r0) * RR) + cc;
    float* intrap = intra + (((size_t)b * RR + r0) * RR) + cc;

    for (int r = r0; r < r0 + ROWS_PER; r += 2) {
        const float* arow0 = &sE[r * RSTRIDE];
        const float* arow1 = &sE[(r + 1) * RSTRIDE];
        ull x0 = 0, x1 = 0, x2 = 0, x3 = 0;   // row r chain
        ull y0 = 0, y1 = 0, y2 = 0, y3 = 0;   // row r+1 chain
        #pragma unroll
        for (int q = 0; q < 4; q++) {
            ulonglong2 ap = *reinterpret_cast<const ulonglong2*>(arow0 + 4 * q);      // LDS.128 bcast
            ulonglong2 aq = *reinterpret_cast<const ulonglong2*>(arow0 + 16 + 4 * q);
            ulonglong2 bp = *reinterpret_cast<const ulonglong2*>(arow1 + 4 * q);
            ulonglong2 bq = *reinterpret_cast<const ulonglong2*>(arow1 + 16 + 4 * q);
            x0 = fma2(ap.x, bv[2 * q],     x0);
            x1 = fma2(ap.y, bv[2 * q + 1], x1);
            x2 = fma2(aq.x, bv[8 + 2 * q],     x2);
            x3 = fma2(aq.y, bv[8 + 2 * q + 1], x3);
            y0 = fma2(bp.x, bv[2 * q],     y0);
            y1 = fma2(bp.y, bv[2 * q + 1], y1);
            y2 = fma2(bq.x, bv[8 + 2 * q],     y2);
            y3 = fma2(bq.y, bv[8 + 2 * q + 1], y3);
        }
        float v0 = sum2(add2(add2(x0, x1), add2(x2, x3)));
        float v1 = sum2(add2(add2(y0, y1), add2(y2, y3)));
        if (active) {
            adjp[0]  = v0;
            adjp[RR] = v1;
            intrap[0]  = (r     >= lo && r     < hi) ? v0 : 0.0f;
            intrap[RR] = (r + 1 >= lo && r + 1 < hi) ? v1 : 0.0f;
        }
        adjp   += 2 * RR;
        intrap += 2 * RR;
    }

    // ---- inter-network block means, only split-0 CTAs (one per batch) ----
    if (split == 0) {
        for (int i = tid; i < SS * KK; i += NTHREADS) {
            int s  = i >> 5;
            int d  = i & 31;
            int st = (s == 0) ? 0 : c_ends[s - 1];
            int en = c_ends[s];
            float a = 0.0f;
            for (int rr2 = st; rr2 < en; rr2++) a += sE[rr2 * RSTRIDE + d];
            sSum[i] = a;
        }
        __syncthreads();
        if (tid < SS * SS) {
            int s = tid / SS, t = tid % SS;
            float a = 0.0f;
            #pragma unroll
            for (int d = 0; d < KK; d++)
                a += sSum[s * KK + d] * sSum[t * KK + d];
            inter[(size_t)b * SS * SS + tid] = a / (c_sizes[s] * c_sizes[t]);
        }
    }
}

extern "C" void kernel_launch(void* const* d_in, const int* in_sizes, int n_in,
                              void* d_out, int out_size)
{
    (void)in_sizes; (void)n_in; (void)out_size;
    const float* E = (const float*)d_in[0];
    float* out = (float*)d_out;

    dim3 grid(NSPLIT, BB);
    size_t smem = (size_t)RR * RSTRIDE * sizeof(float);
    gram_kernel<<<grid, NTHREADS, smem>>>(E, out);
}